// round 1
// baseline (speedup 1.0000x reference)
#include <cuda_runtime.h>
#include <cstdint>
#include <math.h>

// Problem shapes (fixed for this bench)
#define BATCH 2
#define DK 128
#define DV 512
#define NQ 4096         // H*W
#define NM 8192         // T*H*W
#define QT 32           // q per CTA
#define MC 64           // m per chunk
#define NTHREADS 256
#define PSCALAR 40.0f
#define SKIP_LN 27.6310211159f   // -ln(1e-12)

// -------- device scratch (static: no allocations allowed) --------
__device__ float g_S[(size_t)BATCH * NQ * NM];   // 256 MB logits scratch
__device__ float g_qk[BATCH * DK * NQ];          // compacted qkey
__device__ float g_mk[BATCH * DK * NM];          // compacted mkey
__device__ int   g_qlist[BATCH * NQ];
__device__ int   g_mlist[BATCH * NM];
__device__ int   g_nq[BATCH];
__device__ int   g_nm[BATCH];

// -------- kernel 0: zero the output --------
__global__ void zero_kernel(float4* out, int n4) {
    int i = blockIdx.x * blockDim.x + threadIdx.x;
    if (i < n4) out[i] = make_float4(0.f, 0.f, 0.f, 0.f);
}

// -------- kernel 1: deterministic stream compaction of masks --------
// masks assumed stored as 4-byte elements (int32 or float32 bool); nonzero == true
__global__ void compact_kernel(const unsigned int* qmask, const unsigned int* mmask) {
    int b = blockIdx.x;        // batch
    int which = blockIdx.y;    // 0 = q, 1 = m
    const unsigned int* mask = which ? (mmask + b * NM) : (qmask + b * NQ);
    int n = which ? NM : NQ;
    int* list = which ? (g_mlist + b * NM) : (g_qlist + b * NQ);

    __shared__ int wcnt[NTHREADS / 32];
    __shared__ int sbase;
    int tid = threadIdx.x, lane = tid & 31, wid = tid >> 5;
    if (tid == 0) sbase = 0;
    __syncthreads();

    for (int start = 0; start < n; start += NTHREADS) {
        int idx = start + tid;
        int flag = (idx < n) && (mask[idx] != 0u);
        unsigned bal = __ballot_sync(0xFFFFFFFFu, flag);
        int pre = __popc(bal & ((1u << lane) - 1u));
        if (lane == 0) wcnt[wid] = __popc(bal);
        __syncthreads();
        int wbase = 0, tot = 0;
#pragma unroll
        for (int w = 0; w < NTHREADS / 32; w++) {
            if (w < wid) wbase += wcnt[w];
            tot += wcnt[w];
        }
        int base = sbase;
        if (flag) list[base + wbase + pre] = idx;
        __syncthreads();
        if (tid == 0) sbase = base + tot;
        __syncthreads();
    }
    if (tid == 0) {
        if (which) g_nm[b] = sbase; else g_nq[b] = sbase;
    }
}

// -------- kernel 2: gather-pack qkey/mkey into compacted contiguous layout --------
__global__ void pack_kernel(const float* qkey, const float* mkey) {
    int d = blockIdx.x;
    int b = blockIdx.y;
    int nq = g_nq[b], nm = g_nm[b];
    const float* qs = qkey + (size_t)(b * DK + d) * NQ;
    const float* ms = mkey + (size_t)(b * DK + d) * NM;
    float* qd = g_qk + (size_t)(b * DK + d) * NQ;
    float* md = g_mk + (size_t)(b * DK + d) * NM;
    for (int i = threadIdx.x; i < nq; i += blockDim.x) qd[i] = qs[g_qlist[b * NQ + i]];
    for (int i = threadIdx.x; i < nm; i += blockDim.x) md[i] = ms[g_mlist[b * NM + i]];
}

// -------- kernel 3: fused QK GEMM + exact thresholded softmax + sparse PV --------
__global__ __launch_bounds__(NTHREADS)
void attn_kernel(const float* __restrict__ mval, float* __restrict__ out) {
    int b = blockIdx.y;
    int nq = g_nq[b], nm = g_nm[b];
    int qi0 = blockIdx.x * QT;
    if (nm == 0 || qi0 >= nq) return;
    int qn = min(QT, nq - qi0);

    extern __shared__ float sm[];
    float* sQ   = sm;                      // DK*QT        = 4096 f
    float* sM   = sQ + DK * QT;            // 2*DK*MC      = 16384 f
    float* sO   = sM + 2 * DK * MC;        // QT*513       = 16416 f (padded rows)
    float* sMax = sO + QT * 513;           // QT
    float* sSum = sMax + QT;               // QT
    __shared__ int sQg[QT];

    int tid = threadIdx.x;
    int lane = tid & 31, wid = tid >> 5;
    int tx = tid & 15;          // m sub-tile (4 m each)
    int ty = tid >> 4;          // q pair (2 q each)

    // load q global indices
    if (tid < QT) sQg[tid] = (tid < qn) ? g_qlist[b * NQ + qi0 + tid] : 0;
    // load sQ [d][q], zero-pad invalid q
    for (int e = tid; e < DK * QT; e += NTHREADS) {
        int d = e >> 5, q = e & 31;
        sQ[e] = (q < qn) ? g_qk[(size_t)(b * DK + d) * NQ + qi0 + q] : 0.f;
    }
    // zero output accumulator
    for (int e = tid; e < QT * 513; e += NTHREADS) sO[e] = 0.f;

    // ---- phase 1: QK logits, write to scratch, track per-q max ----
    int nch = (nm + MC - 1) / MC;
    float rmax0 = -3.0e38f, rmax1 = -3.0e38f;
    size_t rowbase = (size_t)(b * NQ + qi0) * NM;

    // preload chunk 0
    {
#pragma unroll
        for (int k = 0; k < 8; k++) {
            int e = tid + k * NTHREADS;
            int d = e >> 4, j4 = e & 15;
            float4 v = *(const float4*)&g_mk[(size_t)(b * DK + d) * NM + j4 * 4];
            *(float4*)&sM[d * MC + j4 * 4] = v;
        }
    }
    __syncthreads();

    for (int c = 0; c < nch; c++) {
        int mb = c * MC;
        // fetch next chunk into registers (overlaps with compute)
        float4 stage[8];
        if (c + 1 < nch) {
            int mbn = mb + MC;
#pragma unroll
            for (int k = 0; k < 8; k++) {
                int e = tid + k * NTHREADS;
                int d = e >> 4, j4 = e & 15;
                stage[k] = *(const float4*)&g_mk[(size_t)(b * DK + d) * NM + mbn + j4 * 4];
            }
        }

        const float* sMb = sM + (c & 1) * DK * MC;
        float a00 = 0.f, a01 = 0.f, a02 = 0.f, a03 = 0.f;
        float a10 = 0.f, a11 = 0.f, a12 = 0.f, a13 = 0.f;
#pragma unroll 8
        for (int d = 0; d < DK; d++) {
            float4 m4 = *(const float4*)&sMb[d * MC + (tx << 2)];
            float2 q2 = *(const float2*)&sQ[d * QT + (ty << 1)];
            a00 += q2.x * m4.x; a01 += q2.x * m4.y; a02 += q2.x * m4.z; a03 += q2.x * m4.w;
            a10 += q2.y * m4.x; a11 += q2.y * m4.y; a12 += q2.y * m4.z; a13 += q2.y * m4.w;
        }

        int mbase = mb + (tx << 2);
        // q = ty*2 + 0
        {
            float4 sv;
            sv.x = a00 * PSCALAR; sv.y = a01 * PSCALAR; sv.z = a02 * PSCALAR; sv.w = a03 * PSCALAR;
            if (mbase + 3 < nm) {
                rmax0 = fmaxf(rmax0, fmaxf(fmaxf(sv.x, sv.y), fmaxf(sv.z, sv.w)));
            } else {
                if (mbase + 0 < nm) rmax0 = fmaxf(rmax0, sv.x);
                if (mbase + 1 < nm) rmax0 = fmaxf(rmax0, sv.y);
                if (mbase + 2 < nm) rmax0 = fmaxf(rmax0, sv.z);
                if (mbase + 3 < nm) rmax0 = fmaxf(rmax0, sv.w);
            }
            *(float4*)&g_S[rowbase + (size_t)((ty << 1) + 0) * NM + mbase] = sv;
        }
        // q = ty*2 + 1
        {
            float4 sv;
            sv.x = a10 * PSCALAR; sv.y = a11 * PSCALAR; sv.z = a12 * PSCALAR; sv.w = a13 * PSCALAR;
            if (mbase + 3 < nm) {
                rmax1 = fmaxf(rmax1, fmaxf(fmaxf(sv.x, sv.y), fmaxf(sv.z, sv.w)));
            } else {
                if (mbase + 0 < nm) rmax1 = fmaxf(rmax1, sv.x);
                if (mbase + 1 < nm) rmax1 = fmaxf(rmax1, sv.y);
                if (mbase + 2 < nm) rmax1 = fmaxf(rmax1, sv.z);
                if (mbase + 3 < nm) rmax1 = fmaxf(rmax1, sv.w);
            }
            *(float4*)&g_S[rowbase + (size_t)((ty << 1) + 1) * NM + mbase] = sv;
        }

        if (c + 1 < nch) {
            __syncthreads();
            float* sMd = sM + ((c + 1) & 1) * DK * MC;
#pragma unroll
            for (int k = 0; k < 8; k++) {
                int e = tid + k * NTHREADS;
                int d = e >> 4, j4 = e & 15;
                *(float4*)&sMd[d * MC + j4 * 4] = stage[k];
            }
            __syncthreads();
        }
    }

    // reduce per-q max across the 16 tx lanes sharing the same ty
#pragma unroll
    for (int off = 8; off > 0; off >>= 1) {
        rmax0 = fmaxf(rmax0, __shfl_xor_sync(0xFFFFFFFFu, rmax0, off));
        rmax1 = fmaxf(rmax1, __shfl_xor_sync(0xFFFFFFFFu, rmax1, off));
    }
    if (tx == 0) {
        sMax[(ty << 1) + 0] = rmax0;
        sMax[(ty << 1) + 1] = rmax1;
    }
    __syncthreads();

    // ---- phase 2: exact thresholded softmax + sparse mval gather ----
    const float* mvb = mval + (size_t)b * DV * NM;
    for (int k = 0; k < 4; k++) {
        int q = wid * 4 + k;
        if (q >= qn) continue;   // uniform per warp
        float qmax = sMax[q];
        float thresh = qmax - SKIP_LN;
        const float* Srow = &g_S[rowbase + (size_t)q * NM];
        float* orow = &sO[q * 513];
        float sum = 0.f;
        for (int mb2 = 0; mb2 < nm; mb2 += 32) {
            int mi = mb2 + lane;
            bool in = (mi < nm);
            float s = in ? Srow[mi] : -3.0e38f;
            float w = 0.f;
            bool ev = in && (s > thresh);
            if (ev) { w = __expf(s - qmax); sum += w; }
            unsigned bal = __ballot_sync(0xFFFFFFFFu, ev);
            while (bal) {
                int src = __ffs(bal) - 1;
                bal &= bal - 1;
                float we = __shfl_sync(0xFFFFFFFFu, w, src);
                int mie = __shfl_sync(0xFFFFFFFFu, mi, src);
                int mg = g_mlist[b * NM + mie];
                const float* col = mvb + mg;
#pragma unroll
                for (int j = 0; j < 16; j++) {
                    int v = lane + j * 32;
                    orow[v] += we * col[(size_t)v * NM];
                }
            }
        }
#pragma unroll
        for (int off = 16; off > 0; off >>= 1)
            sum += __shfl_xor_sync(0xFFFFFFFFu, sum, off);
        if (lane == 0) sSum[q] = sum;
    }
    __syncthreads();

    // ---- write out: out[b][v][qg] = sO[q][v] / sum ----
    if (lane < qn) {
        float inv = 1.0f / sSum[lane];
        int qg = sQg[lane];
#pragma unroll 8
        for (int j = 0; j < DV / 8; j++) {
            int v = wid * (DV / 8) + j;
            out[(size_t)(b * DV + v) * NQ + qg] = sO[lane * 513 + v] * inv;
        }
    }
}

// -------- launch --------
extern "C" void kernel_launch(void* const* d_in, const int* in_sizes, int n_in,
                              void* d_out, int out_size) {
    const float*        qkey  = (const float*)d_in[0];
    // d_in[1] = qval (unused by the reference math)
    const unsigned int* qmask = (const unsigned int*)d_in[2];
    const float*        mkey  = (const float*)d_in[3];
    const float*        mval  = (const float*)d_in[4];
    const unsigned int* mmask = (const unsigned int*)d_in[5];
    float* out = (float*)d_out;

    // zero output (invalid queries / batches must be 0)
    int n4 = BATCH * DV * NQ / 4;
    zero_kernel<<<(n4 + 255) / 256, 256>>>((float4*)out, n4);

    // compact masks
    compact_kernel<<<dim3(BATCH, 2), NTHREADS>>>(qmask, mmask);

    // pack qk / mk
    pack_kernel<<<dim3(DK, BATCH), NTHREADS>>>(qkey, mkey);

    // main fused kernel
    size_t smemBytes = (size_t)(DK * QT + 2 * DK * MC + QT * 513 + QT + QT) * sizeof(float);
    cudaFuncSetAttribute(attn_kernel, cudaFuncAttributeMaxDynamicSharedMemorySize, (int)smemBytes);
    attn_kernel<<<dim3(NQ / QT, BATCH), NTHREADS, smemBytes>>>(mval, out);
}

// round 2
// speedup vs baseline: 2.2723x; 2.2723x over previous
#include <cuda_runtime.h>
#include <cstdint>
#include <math.h>

// Problem shapes (fixed for this bench)
#define BATCH 2
#define DK 128
#define DV 512
#define NQ 4096         // H*W
#define NM 8192         // T*H*W
#define NTHREADS 256
#define PSCALAR 40.0f
#define DELTA 27.6310211159f     // -ln(1e-12)

// GEMM tiling
#define QTILE 128
#define MC 128
#define NSEG 4
#define CAP 1024

// -------- device scratch (static: no allocations allowed) --------
__device__ float g_qk[BATCH * DK * NQ];          // compacted qkey
__device__ float g_mk[BATCH * DK * NM];          // compacted mkey
__device__ int   g_qlist[BATCH * NQ];
__device__ int   g_mlist[BATCH * NM];
__device__ int   g_nq[BATCH];
__device__ int   g_nm[BATCH];
__device__ int2  g_cand[(size_t)BATCH * NQ * CAP];  // (m_compact, logit bits) 64MB
__device__ int   g_ccnt[BATCH * NQ];

// monotone float<->uint encoding for atomicMax on floats (incl. negatives)
__device__ __forceinline__ unsigned fenc(float f) {
    unsigned u = __float_as_uint(f);
    return (u & 0x80000000u) ? ~u : (u | 0x80000000u);
}
__device__ __forceinline__ float fdec(unsigned e) {
    unsigned u = (e & 0x80000000u) ? (e & 0x7FFFFFFFu) : ~e;
    return __uint_as_float(u);
}

// -------- kernel 0: zero output + candidate counters --------
__global__ void zero_kernel(float4* out, int n4) {
    int i = blockIdx.x * blockDim.x + threadIdx.x;
    if (i < n4) out[i] = make_float4(0.f, 0.f, 0.f, 0.f);
    if (i < BATCH * NQ / 4) ((int4*)g_ccnt)[i] = make_int4(0, 0, 0, 0);
}

// -------- kernel 1: deterministic stream compaction of masks --------
__global__ void compact_kernel(const unsigned int* qmask, const unsigned int* mmask) {
    int b = blockIdx.x;
    int which = blockIdx.y;    // 0 = q, 1 = m
    const unsigned int* mask = which ? (mmask + b * NM) : (qmask + b * NQ);
    int n = which ? NM : NQ;
    int* list = which ? (g_mlist + b * NM) : (g_qlist + b * NQ);

    __shared__ int wcnt[NTHREADS / 32];
    __shared__ int sbase;
    int tid = threadIdx.x, lane = tid & 31, wid = tid >> 5;
    if (tid == 0) sbase = 0;
    __syncthreads();

    for (int start = 0; start < n; start += NTHREADS) {
        int idx = start + tid;
        int flag = (idx < n) && (mask[idx] != 0u);
        unsigned bal = __ballot_sync(0xFFFFFFFFu, flag);
        int pre = __popc(bal & ((1u << lane) - 1u));
        if (lane == 0) wcnt[wid] = __popc(bal);
        __syncthreads();
        int wbase = 0, tot = 0;
#pragma unroll
        for (int w = 0; w < NTHREADS / 32; w++) {
            if (w < wid) wbase += wcnt[w];
            tot += wcnt[w];
        }
        int base = sbase;
        if (flag) list[base + wbase + pre] = idx;
        __syncthreads();
        if (tid == 0) sbase = base + tot;
        __syncthreads();
    }
    if (tid == 0) {
        if (which) g_nm[b] = sbase; else g_nq[b] = sbase;
    }
}

// -------- kernel 2: gather-pack qkey/mkey; zero-fill padded tails --------
__global__ void pack_kernel(const float* qkey, const float* mkey) {
    int d = blockIdx.x;
    int b = blockIdx.y;
    int nq = g_nq[b], nm = g_nm[b];
    const float* qs = qkey + (size_t)(b * DK + d) * NQ;
    const float* ms = mkey + (size_t)(b * DK + d) * NM;
    float* qd = g_qk + (size_t)(b * DK + d) * NQ;
    float* md = g_mk + (size_t)(b * DK + d) * NM;
    for (int i = threadIdx.x; i < nq; i += blockDim.x) qd[i] = qs[g_qlist[b * NQ + i]];
    for (int i = nq + threadIdx.x; i < NQ; i += blockDim.x) qd[i] = 0.f;
    for (int i = threadIdx.x; i < nm; i += blockDim.x) md[i] = ms[g_mlist[b * NM + i]];
    for (int i = nm + threadIdx.x; i < NM; i += blockDim.x) md[i] = 0.f;
}

// -------- kernel 3: QK GEMM + inline running-max candidate emission --------
__global__ __launch_bounds__(NTHREADS, 1)
void qk_kernel() {
    int b = blockIdx.z, seg = blockIdx.y;
    int nq = g_nq[b], nm = g_nm[b];
    int qi0 = blockIdx.x * QTILE;
    if (qi0 >= nq || nm == 0) return;
    int segsz = (((nm + NSEG - 1) / NSEG) + MC - 1) / MC * MC;
    int ms = seg * segsz;
    if (ms >= nm) return;
    int me = min(ms + segsz, nm);

    extern __shared__ float sm[];
    float* sQ = sm;                          // [DK][QTILE] 64KB
    float* sM = sQ + DK * QTILE;             // 2 x [DK][MC] 128KB
    unsigned* sGMax = (unsigned*)(sM + 2 * DK * MC);  // [QTILE]

    int tid = threadIdx.x;
    int tx = tid & 15;       // m: 8 each
    int ty = tid >> 4;       // q: 8 each

    if (tid < QTILE) sGMax[tid] = fenc(-3.0e38f);

    const float* qkb = g_qk + (size_t)b * DK * NQ;
    const float* mkb = g_mk + (size_t)b * DK * NM;

    // load sQ (zero-pad beyond nq — already padded in g_qk, direct copy is fine)
    for (int e = tid; e < DK * QTILE; e += NTHREADS) {
        int d = e >> 7, q = e & 127;
        sQ[e] = qkb[(size_t)d * NQ + qi0 + q];
    }

    int nch = (me - ms + MC - 1) / MC;

    // cp.async issue of one mk chunk [DK][MC] into buffer `buf`
    auto issue = [&](int m0, int buf) {
        float* dst = sM + buf * DK * MC;
#pragma unroll
        for (int k = 0; k < 16; k++) {
            int idx = tid + k * NTHREADS;     // 4096 float4s
            int d = idx >> 5, j = idx & 31;
            const float* src = &mkb[(size_t)d * NM + m0 + j * 4];
            unsigned saddr = (unsigned)__cvta_generic_to_shared(&dst[d * MC + j * 4]);
            asm volatile("cp.async.cg.shared.global [%0], [%1], 16;" :: "r"(saddr), "l"(src));
        }
        asm volatile("cp.async.commit_group;");
    };

    issue(ms, 0);

    float cth[8];
#pragma unroll
    for (int j = 0; j < 8; j++) cth[j] = -3.0e38f;

    for (int c = 0; c < nch; c++) {
        int m0 = ms + c * MC;
        asm volatile("cp.async.wait_group 0;");
        __syncthreads();
        if (c + 1 < nch) issue(ms + (c + 1) * MC, (c + 1) & 1);

        const float* sMb = sM + (c & 1) * DK * MC;

        // refresh cached running-max thresholds
#pragma unroll
        for (int j = 0; j < 8; j++) cth[j] = fdec(sGMax[ty * 8 + j]);

        float acc[8][8];
#pragma unroll
        for (int j = 0; j < 8; j++)
#pragma unroll
            for (int i = 0; i < 8; i++) acc[j][i] = 0.f;

#pragma unroll 4
        for (int d = 0; d < DK; d++) {
            float4 m0v = *(const float4*)&sMb[d * MC + tx * 8];
            float4 m1v = *(const float4*)&sMb[d * MC + tx * 8 + 4];
            float4 q0v = *(const float4*)&sQ[d * QTILE + ty * 8];
            float4 q1v = *(const float4*)&sQ[d * QTILE + ty * 8 + 4];
            float mm[8] = {m0v.x, m0v.y, m0v.z, m0v.w, m1v.x, m1v.y, m1v.z, m1v.w};
            float qq[8] = {q0v.x, q0v.y, q0v.z, q0v.w, q1v.x, q1v.y, q1v.z, q1v.w};
#pragma unroll
            for (int j = 0; j < 8; j++)
#pragma unroll
                for (int i = 0; i < 8; i++)
                    acc[j][i] += qq[j] * mm[i];
        }

        // epilogue: scale, per-q block max, rare candidate insertion
#pragma unroll
        for (int j = 0; j < 8; j++) {
            float bm = -3.0e38f;
#pragma unroll
            for (int i = 0; i < 8; i++) {
                acc[j][i] *= PSCALAR;
                bm = fmaxf(bm, acc[j][i]);
            }
            if (bm > cth[j] - DELTA) {
                int q = qi0 + ty * 8 + j;
                if (q < nq) {
                    unsigned olde = atomicMax(&sGMax[ty * 8 + j], fenc(bm));
                    float th = fmaxf(fdec(olde), bm);
                    cth[j] = th;
#pragma unroll
                    for (int i = 0; i < 8; i++) {
                        int mg = m0 + tx * 8 + i;
                        if (mg < me && acc[j][i] > th - DELTA) {
                            int pos = atomicAdd(&g_ccnt[b * NQ + q], 1);
                            if (pos < CAP)
                                g_cand[((size_t)b * NQ + q) * CAP + pos] =
                                    make_int2(mg, __float_as_int(acc[j][i]));
                        }
                    }
                } else {
                    cth[j] = fmaxf(cth[j], bm);  // phantom q: local suppress
                }
            }
        }
    }
}

// -------- kernel 4: finalize — exact max/sum + deterministic sparse gather --------
__global__ __launch_bounds__(NTHREADS)
void finalize_kernel(const float* __restrict__ mval, float* __restrict__ out) {
    int b = blockIdx.y;
    int nq = g_nq[b], nm = g_nm[b];
    int wid = threadIdx.x >> 5, lane = threadIdx.x & 31;
    int q = blockIdx.x * 8 + wid;
    if (q >= nq || nm == 0) return;

    size_t cbase = ((size_t)b * NQ + q) * CAP;
    int c = min(g_ccnt[b * NQ + q], CAP);

    // pass 1: exact max (order-free)
    float mx = -3.0e38f;
    for (int i = lane; i < c; i += 32)
        mx = fmaxf(mx, __int_as_float(g_cand[cbase + i].y));
#pragma unroll
    for (int off = 16; off; off >>= 1)
        mx = fmaxf(mx, __shfl_xor_sync(0xFFFFFFFFu, mx, off));

    // pass 2: deterministic fixed-point exp sum
    unsigned long long iacc = 0;
    for (int i = lane; i < c; i += 32) {
        float s = __int_as_float(g_cand[cbase + i].y);
        if (s > mx - DELTA) {
            float w = expf(s - mx);
            iacc += (unsigned long long)((double)w * 4503599627370496.0);  // 2^52
        }
    }
#pragma unroll
    for (int off = 16; off; off >>= 1)
        iacc += __shfl_xor_sync(0xFFFFFFFFu, iacc, off);
    double dsum = (double)iacc * (1.0 / 4503599627370496.0);
    float inv = (float)(1.0 / dsum);

    // pass 3: extract passing events in ascending-m order, gather mval columns
    float ov[16];
#pragma unroll
    for (int j = 0; j < 16; j++) ov[j] = 0.f;

    const float* mvb = mval + (size_t)b * DV * NM;
    int last = -1;
    while (true) {
        int mym = 0x7FFFFFFF; float myw = 0.f;
        for (int i = lane; i < c; i += 32) {
            int2 e = g_cand[cbase + i];
            float s = __int_as_float(e.y);
            if (s > mx - DELTA && e.x > last && e.x < mym) {
                mym = e.x;
                myw = expf(s - mx);
            }
        }
#pragma unroll
        for (int off = 16; off; off >>= 1) {
            int om = __shfl_xor_sync(0xFFFFFFFFu, mym, off);
            float ow = __shfl_xor_sync(0xFFFFFFFFu, myw, off);
            if (om < mym) { mym = om; myw = ow; }
        }
        if (mym == 0x7FFFFFFF) break;
        int mg = g_mlist[b * NM + mym];
        const float* col = mvb + mg;
#pragma unroll
        for (int j = 0; j < 16; j++)
            ov[j] += myw * col[(size_t)(lane + 32 * j) * NM];
        last = mym;
    }

    int qg = g_qlist[b * NQ + q];
    float* ob = out + (size_t)b * DV * NQ + qg;
#pragma unroll
    for (int j = 0; j < 16; j++)
        ob[(size_t)(lane + 32 * j) * NQ] = ov[j] * inv;
}

// -------- launch --------
extern "C" void kernel_launch(void* const* d_in, const int* in_sizes, int n_in,
                              void* d_out, int out_size) {
    const float*        qkey  = (const float*)d_in[0];
    // d_in[1] = qval (unused by the reference math)
    const unsigned int* qmask = (const unsigned int*)d_in[2];
    const float*        mkey  = (const float*)d_in[3];
    const float*        mval  = (const float*)d_in[4];
    const unsigned int* mmask = (const unsigned int*)d_in[5];
    float* out = (float*)d_out;

    int n4 = BATCH * DV * NQ / 4;
    zero_kernel<<<(n4 + 255) / 256, 256>>>((float4*)out, n4);

    compact_kernel<<<dim3(BATCH, 2), NTHREADS>>>(qmask, mmask);

    pack_kernel<<<dim3(DK, BATCH), NTHREADS>>>(qkey, mkey);

    size_t smemBytes = (size_t)(DK * QTILE + 2 * DK * MC) * sizeof(float) + QTILE * sizeof(unsigned);
    cudaFuncSetAttribute(qk_kernel, cudaFuncAttributeMaxDynamicSharedMemorySize, (int)smemBytes);
    qk_kernel<<<dim3(NQ / QTILE, NSEG, BATCH), NTHREADS, smemBytes>>>();

    finalize_kernel<<<dim3(NQ / 8, BATCH), NTHREADS>>>(mval, out);
}